// round 14
// baseline (speedup 1.0000x reference)
#include <cuda_runtime.h>
#include <cstdint>

#define NN 32768
#define KK 4000
#define DD 128
#define CC 1000

#define BM 128
#define BN 64              // proxies per tile
#define NTILES 64          // 4096 padded proxies / 64
#define KPAD (NTILES*BN)
#define NSPLIT 4           // K split: 4 quarters x 16 tiles
#define TPQ (NTILES/NSPLIT)
#define TM 8               // rows per thread (4 f32x2 pairs)
#define TN 4               // proxies per thread
#define NTHREADS 256

__device__ float g_x2[NN];
__device__ float g_p2[KPAD];
__device__ int   g_idx[NN];
__device__ __align__(16) float g_xT[DD * NN];        // x transposed [d][row], 16MB
__device__ __align__(16) float g_pD[KPAD * DD * 2];  // proxies duplicated: [tile][d][k2], 4MB
__device__ float g_partv[NSPLIT * NN];
__device__ int   g_parti[NSPLIT * NN];

// ---------------- packed f32x2 helpers ----------------
__device__ __forceinline__ uint64_t ffma2(uint64_t a, uint64_t b, uint64_t c) {
    uint64_t d;
    asm("fma.rn.f32x2 %0, %1, %2, %3;" : "=l"(d) : "l"(a), "l"(b), "l"(c));
    return d;
}
__device__ __forceinline__ float2 unpack2(uint64_t v) {
    float2 r;
    asm("mov.b64 {%0, %1}, %2;" : "=f"(r.x), "=f"(r.y) : "l"(v));
    return r;
}
__device__ __forceinline__ uint32_t smem_u32(const void* p) {
    uint32_t a;
    asm("{ .reg .u64 t; cvta.to.shared.u64 t, %1; cvt.u32.u64 %0, t; }" : "=r"(a) : "l"(p));
    return a;
}
__device__ __forceinline__ void cpa16(uint32_t dst, const void* src) {
    asm volatile("cp.async.cg.shared.global [%0], [%1], 16;" :: "r"(dst), "l"(src));
}
#define CP_COMMIT() asm volatile("cp.async.commit_group;")
#define CP_WAIT(n)  asm volatile("cp.async.wait_group %0;" :: "n"(n))

// 64KB tile copy: 4096 x 16B chunks, 256 threads -> 16 each
__device__ __forceinline__ void copy_tile_64k(uint32_t dst, const char* src, int tid) {
#pragma unroll
    for (int j = 0; j < 16; j++) {
        int i = tid + NTHREADS * j;
        cpa16(dst + i * 16, src + i * 16);
    }
}

// ---------------- prep: transpose x ----------------
__global__ void prep_x_kernel(const float* __restrict__ x) {
    int c = blockIdx.x * 256 + threadIdx.x;
    int row = c & (NN - 1);
    int d0  = (c >> 15) << 2;
    float4 v = *(const float4*)(x + (size_t)row * DD + d0);
    g_xT[(size_t)(d0 + 0) * NN + row] = v.x;
    g_xT[(size_t)(d0 + 1) * NN + row] = v.y;
    g_xT[(size_t)(d0 + 2) * NN + row] = v.z;
    g_xT[(size_t)(d0 + 3) * NN + row] = v.w;
}

// ---------------- prep: proxies -> duplicated transposed tiles --------------
// layout: g_pD[tile][d][k_in_tile*2 + {0,1}], value duplicated in the pair
__global__ void prep_p_kernel(const float* __restrict__ p) {
    int c = blockIdx.x * 256 + threadIdx.x;   // KPAD*16 chunks of 8 dims
    int k = c >> 4, d0 = (c & 15) << 3;
    float v[8];
    if (k < KK) {
        *(float4*)&v[0] = *(const float4*)(p + (size_t)k * DD + d0);
        *(float4*)&v[4] = *(const float4*)(p + (size_t)k * DD + d0 + 4);
    } else {
#pragma unroll
        for (int i = 0; i < 8; i++) v[i] = 0.f;
        if (d0 == 0) g_p2[k] = 3.0e38f;       // pad sentinel: never wins
    }
    int tile = k >> 6, kin = k & 63;
    float* base = g_pD + (size_t)tile * (DD * BN * 2) + kin * 2;
#pragma unroll
    for (int i = 0; i < 8; i++) {
        float2 dup = make_float2(v[i], v[i]);
        *(float2*)(base + (size_t)(d0 + i) * (BN * 2)) = dup;
    }
}

// ---------------- row squared norms ----------------
__global__ void row_norm_kernel(const float* __restrict__ A, float* __restrict__ out, int rows) {
    int row  = blockIdx.x * 8 + (threadIdx.x >> 5);
    int lane = threadIdx.x & 31;
    if (row >= rows) return;
    const float* a = A + (size_t)row * DD;
    float s = 0.f;
#pragma unroll
    for (int i = 0; i < DD / 32; i++) { float v = a[lane + 32 * i]; s = fmaf(v, v, s); }
#pragma unroll
    for (int o = 16; o > 0; o >>= 1) s += __shfl_down_sync(0xffffffffu, s, o);
    if (lane == 0) out[row] = s;
}

// ---------------- smem layout (floats) ----------------
#define FO_A   0                        // [DD][128]           = 16384 floats
#define FO_B   (DD * 128)               // 2 x [DD][64 pairs]  = 2 x 16384 floats
#define FO_P2  (FO_B + 2 * DD * 128)    // 2 x 64
#define FO_X2  (FO_P2 + 2 * BN)         // 128
#define SMEM_FLOATS (FO_X2 + BM)
#define SMEM_BYTES  (SMEM_FLOATS * 4)   // 197,632 B

extern __shared__ float sm[];

// ---------------- fused score-GEMM + running argmin (one K quarter) ---------
// f32x2 pair = (row r, row r+1); B operand pre-duplicated (k,k). Zero packing.
__global__ __launch_bounds__(NTHREADS, 1)
void argmin_kernel() {
    float* As  = sm + FO_A;
    float* Bs  = sm + FO_B;
    float* p2s = sm + FO_P2;
    float* x2s = sm + FO_X2;
    uint32_t sbA = smem_u32(sm + FO_A);
    uint32_t sbB = smem_u32(sm + FO_B);

    int tid = threadIdx.x;
    int tx  = tid & 15;      // proxy group (TN=4)
    int ty  = tid >> 4;      // row group   (TM=8)
    int rowBase = blockIdx.x * BM;
    int q       = blockIdx.y;
    int t0      = q * TPQ;

    // --- prologue: A tile + B tiles t0, t0+1 ---
    {
        const char* srcA0 = (const char*)(g_xT + rowBase);
#pragma unroll
        for (int j = 0; j < 16; j++) {
            int i = tid + NTHREADS * j;
            int d = i >> 5, c = i & 31;
            cpa16(sbA + (d * 128 + c * 4) * 4, srcA0 + ((size_t)d * NN + c * 4) * 4);
        }
        copy_tile_64k(sbB, (const char*)(g_pD + (size_t)t0 * (DD * BN * 2)), tid);
        if (tid < BN) p2s[tid] = g_p2[t0 * BN + tid];
        if (tid < BM) x2s[tid] = g_x2[rowBase + tid];
        CP_COMMIT();
        copy_tile_64k(sbB + DD * 128 * 4,
                      (const char*)(g_pD + (size_t)(t0 + 1) * (DD * BN * 2)), tid);
        if (tid < BN) p2s[BN + tid] = g_p2[(t0 + 1) * BN + tid];
        CP_COMMIT();
    }

    CP_WAIT(1);
    __syncthreads();
    float x2r[TM];
#pragma unroll
    for (int i = 0; i < TM; i++) x2r[i] = x2s[ty * TM + i];

    float bestv[TM]; int besti[TM];
#pragma unroll
    for (int i = 0; i < TM; i++) { bestv[i] = 3.0e38f; besti[i] = 0; }

    for (int tl = 0; tl < TPQ; tl++) {
        int t = t0 + tl;
        int b = tl & 1;
        if (tl > 0) {
            if (tl == TPQ - 1) { CP_WAIT(0); } else { CP_WAIT(1); }
            __syncthreads();
        }

        uint64_t acc[TM / 2][TN];            // [row-pair][k]
#pragma unroll
        for (int i = 0; i < TM / 2; i++)
#pragma unroll
            for (int j = 0; j < TN; j++) acc[i][j] = 0ull;

        const float* xb = As + ty * TM;          // 8 rows = 4 pairs, contiguous
        const float* pb = Bs + b * (DD * 128) + tx * (TN * 2);
#pragma unroll 4
        for (int d = 0; d < DD; d++) {
            ulonglong2 a01 = *(const ulonglong2*)(xb + d * 128);      // pairs r0r1, r2r3
            ulonglong2 a23 = *(const ulonglong2*)(xb + d * 128 + 4);  // pairs r4r5, r6r7
            ulonglong2 b01 = *(const ulonglong2*)(pb + d * 128);      // (k0,k0),(k1,k1)
            ulonglong2 b23 = *(const ulonglong2*)(pb + d * 128 + 4);  // (k2,k2),(k3,k3)
            uint64_t ar[TM / 2] = { a01.x, a01.y, a23.x, a23.y };
            uint64_t bv[TN]     = { b01.x, b01.y, b23.x, b23.y };
#pragma unroll
            for (int i = 0; i < TM / 2; i++)
#pragma unroll
                for (int j = 0; j < TN; j++)
                    acc[i][j] = ffma2(ar[i], bv[j], acc[i][j]);
        }

        // running argmin (k ascending per thread; strict '<' = first-min)
        const float* pp = p2s + b * BN + tx * TN;
#pragma unroll
        for (int j = 0; j < TN; j++) {
            int kg = t * BN + tx * TN + j;
            float pv = pp[j];
#pragma unroll
            for (int i = 0; i < TM / 2; i++) {
                float2 dp = unpack2(acc[i][j]);     // (row 2i, row 2i+1) dots
                float s0 = (x2r[2 * i]     - 2.0f * dp.x) + pv;
                float s1 = (x2r[2 * i + 1] - 2.0f * dp.y) + pv;
                if (s0 < bestv[2 * i])     { bestv[2 * i]     = s0; besti[2 * i]     = kg; }
                if (s1 < bestv[2 * i + 1]) { bestv[2 * i + 1] = s1; besti[2 * i + 1] = kg; }
            }
        }
        __syncthreads();

        if (tl + 2 < TPQ) {
            copy_tile_64k(sbB + b * (DD * 128 * 4),
                          (const char*)(g_pD + (size_t)(t + 2) * (DD * BN * 2)), tid);
            if (tid < BN) p2s[b * BN + tid] = g_p2[(t + 2) * BN + tid];
            CP_COMMIT();
        }
    }

    // --- cross-thread reduction: 16 candidates per row (reuse B region) ---
    float* redv = Bs;                     // [16][BM]
    int*   redi = (int*)(Bs + 16 * BM);   // [16][BM]
#pragma unroll
    for (int i = 0; i < TM; i++) {
        int row = ty * TM + i;
        redv[tx * BM + row] = bestv[i];
        redi[tx * BM + row] = besti[i];
    }
    __syncthreads();
    if (tid < BM) {
        float bv = 3.4e38f; int bi = 0x7fffffff;
#pragma unroll
        for (int t = 0; t < 16; t++) {
            float v  = redv[t * BM + tid];
            int   ix = redi[t * BM + tid];
            if (v < bv || (v == bv && ix < bi)) { bv = v; bi = ix; }
        }
        g_partv[q * NN + rowBase + tid] = bv;
        g_parti[q * NN + rowBase + tid] = bi;
    }
}

// ---------------- merge quarters (disjoint ascending k-ranges) ----------
__global__ void merge_kernel() {
    int row = blockIdx.x * 256 + threadIdx.x;
    float bv = g_partv[row];
    int   bi = g_parti[row];
#pragma unroll
    for (int qq = 1; qq < NSPLIT; qq++) {
        float v  = g_partv[qq * NN + row];
        int   ix = g_parti[qq * NN + row];
        if (v < bv) { bv = v; bi = ix; }
    }
    g_idx[row] = bi;
}

// ---------------- gather ----------------
__global__ void gather_kernel(const float* __restrict__ x, const float* __restrict__ p,
                              const float* __restrict__ lab, float* __restrict__ out) {
    int row = blockIdx.x;
    int tid = threadIdx.x;
    int idx = g_idx[row];

    const float4* xr = (const float4*)(x + (size_t)row * DD);
    float4*       o0 = (float4*)(out + (size_t)row * DD);
    const float4* pr = (const float4*)(p + (size_t)idx * DD);
    float4*       o1 = (float4*)(out + (size_t)NN * DD + (size_t)row * DD);
    const float4* lr = (const float4*)(lab + (size_t)idx * CC);
    float4*       o2 = (float4*)(out + 2 * (size_t)NN * DD + (size_t)row * CC);

    if (tid < 32)       __stcs(o0 + tid,      xr[tid]);
    else if (tid < 64)  __stcs(o1 + tid - 32, pr[tid - 32]);
    for (int i = tid; i < CC / 4; i += blockDim.x) __stcs(o2 + i, lr[i]);
}

// ---------------- launch ----------------
extern "C" void kernel_launch(void* const* d_in, const int* in_sizes, int n_in,
                              void* d_out, int out_size) {
    const float* x   = (const float*)d_in[0];
    const float* p   = (const float*)d_in[1];
    const float* lab = (const float*)d_in[2];
    float* out = (float*)d_out;

    float *px2 = nullptr, *pp2 = nullptr;
    cudaGetSymbolAddress((void**)&px2, g_x2);
    cudaGetSymbolAddress((void**)&pp2, g_p2);

    cudaFuncSetAttribute(argmin_kernel, cudaFuncAttributeMaxDynamicSharedMemorySize, SMEM_BYTES);

    row_norm_kernel<<<NN / 8, 256>>>(x, px2, NN);
    prep_x_kernel<<<NN * 32 / 256, 256>>>(x);
    prep_p_kernel<<<KPAD * 16 / 256, 256>>>(p);
    row_norm_kernel<<<(KK + 7) / 8, 256>>>(p, pp2, KK);
    argmin_kernel<<<dim3(NN / BM, NSPLIT), NTHREADS, SMEM_BYTES>>>();
    merge_kernel<<<NN / 256, 256>>>();
    gather_kernel<<<NN, 256>>>(x, p, lab, out);
}

// round 17
// speedup vs baseline: 1.4994x; 1.4994x over previous
#include <cuda_runtime.h>
#include <cstdint>

#define NN 32768
#define KK 4000
#define DD 128
#define CC 1000

#define BM 128             // rows per CTA tile
#define BN 64              // proxies per B tile
#define NTILES 64          // 4096 padded proxies / 64
#define KPAD (NTILES*BN)
#define NSPLIT 4           // K quarters, 16 tiles each
#define TPQ (NTILES/NSPLIT)
#define TM 8               // rows per thread
#define TN 8               // proxies per thread
#define NTHREADS 128       // 4 warps -> 1 warp per SMSP

__device__ float g_x2[NN];
__device__ float g_p2[KPAD];
__device__ int   g_idx[NN];
__device__ __align__(16) float g_xD[NN * DD * 2];   // x dup-pairs: [blk][d][row*2], 32MB
__device__ __align__(16) float g_pT[KPAD * DD];     // proxies [tile][d][k_in_tile], 2MB
__device__ float g_partv[NSPLIT * NN];
__device__ int   g_parti[NSPLIT * NN];

// ---------------- packed f32x2 helpers ----------------
__device__ __forceinline__ uint64_t ffma2(uint64_t a, uint64_t b, uint64_t c) {
    uint64_t d;
    asm("fma.rn.f32x2 %0, %1, %2, %3;" : "=l"(d) : "l"(a), "l"(b), "l"(c));
    return d;
}
__device__ __forceinline__ float2 unpack2(uint64_t v) {
    float2 r;
    asm("mov.b64 {%0, %1}, %2;" : "=f"(r.x), "=f"(r.y) : "l"(v));
    return r;
}
__device__ __forceinline__ uint32_t smem_u32(const void* p) {
    uint32_t a;
    asm("{ .reg .u64 t; cvta.to.shared.u64 t, %1; cvt.u32.u64 %0, t; }" : "=r"(a) : "l"(p));
    return a;
}
__device__ __forceinline__ void cpa16(uint32_t dst, const void* src) {
    asm volatile("cp.async.cg.shared.global [%0], [%1], 16;" :: "r"(dst), "l"(src));
}
#define CP_COMMIT() asm volatile("cp.async.commit_group;")
#define CP_WAIT(n)  asm volatile("cp.async.wait_group %0;" :: "n"(n))

// 32KB B tile: 2048 x 16B chunks, 128 threads -> 16 each
__device__ __forceinline__ void copy_tile_32k(uint32_t dst, const char* src, int tid) {
#pragma unroll
    for (int j = 0; j < 16; j++) {
        int i = tid + NTHREADS * j;
        cpa16(dst + i * 16, src + i * 16);
    }
}

// ---------------- prep: x -> duplicated pair tiles ----------------
// g_xD layout per 128-row block: [d][row*2 + {0,1}] (256 floats per d-row)
__global__ void prep_x_kernel(const float* __restrict__ x) {
    int c = blockIdx.x * 256 + threadIdx.x;     // NN*32 threads (float4 granules)
    int row = c & (NN - 1);
    int d0  = (c >> 15) << 2;
    float4 v = *(const float4*)(x + (size_t)row * DD + d0);
    int blk = row >> 7, rm = row & 127;
    float* base = g_xD + (size_t)blk * (DD * 256) + rm * 2;
    *(float2*)(base + (size_t)(d0 + 0) * 256) = make_float2(v.x, v.x);
    *(float2*)(base + (size_t)(d0 + 1) * 256) = make_float2(v.y, v.y);
    *(float2*)(base + (size_t)(d0 + 2) * 256) = make_float2(v.z, v.z);
    *(float2*)(base + (size_t)(d0 + 3) * 256) = make_float2(v.w, v.w);
}

// ---------------- prep: proxies -> transposed 64-wide tiles + sentinels ----
__global__ void prep_p_kernel(const float* __restrict__ p) {
    int c = blockIdx.x * 256 + threadIdx.x;     // KPAD*16 chunks of 8 dims
    int k = c >> 4, d0 = (c & 15) << 3;
    float v[8];
    if (k < KK) {
        *(float4*)&v[0] = *(const float4*)(p + (size_t)k * DD + d0);
        *(float4*)&v[4] = *(const float4*)(p + (size_t)k * DD + d0 + 4);
    } else {
#pragma unroll
        for (int i = 0; i < 8; i++) v[i] = 0.f;
        if (d0 == 0) g_p2[k] = 3.0e38f;         // pad sentinel: never wins
    }
    float* base = g_pT + (size_t)(k >> 6) * (DD * BN) + (k & 63);
#pragma unroll
    for (int i = 0; i < 8; i++) base[(size_t)(d0 + i) * BN] = v[i];
}

// ---------------- row squared norms ----------------
__global__ void row_norm_kernel(const float* __restrict__ A, float* __restrict__ out, int rows) {
    int row  = blockIdx.x * 8 + (threadIdx.x >> 5);
    int lane = threadIdx.x & 31;
    if (row >= rows) return;
    const float* a = A + (size_t)row * DD;
    float s = 0.f;
#pragma unroll
    for (int i = 0; i < DD / 32; i++) { float v = a[lane + 32 * i]; s = fmaf(v, v, s); }
#pragma unroll
    for (int o = 16; o > 0; o >>= 1) s += __shfl_down_sync(0xffffffffu, s, o);
    if (lane == 0) out[row] = s;
}

// ---------------- smem layout (floats) ----------------
#define FO_A   0                        // [DD][256] dup-pairs = 32768 floats (128KB)
#define FO_B   (DD * 256)               // 2 x [DD][64] = 2 x 8192 floats (64KB)
#define FO_P2  (FO_B + 2 * DD * BN)     // 2 x 64
#define FO_X2  (FO_P2 + 2 * BN)         // 128
#define SMEM_FLOATS (FO_X2 + BM)
#define SMEM_BYTES  (SMEM_FLOATS * 4)   // 197,632 B

extern __shared__ float sm[];

// ---------------- fused score-GEMM + running argmin (one K quarter) ---------
// A pair = (v_r, v_r) from dup tile (LDS-direct); B pair = (p_k, p_k+1) natural.
// 128 threads, 8 rows x 8 k each; 1 warp/SMSP -> fma-pipe bound with issue slack.
__global__ __launch_bounds__(NTHREADS, 1)
void argmin_kernel() {
    float* As  = sm + FO_A;
    float* Bs  = sm + FO_B;
    float* p2s = sm + FO_P2;
    float* x2s = sm + FO_X2;
    uint32_t sbA = smem_u32(sm + FO_A);
    uint32_t sbB = smem_u32(sm + FO_B);

    int tid = threadIdx.x;
    int tx  = tid & 7;       // proxy group: k = tx*4 + {0..3} and +32
    int ty  = tid >> 3;      // row group: rows ty*8 .. ty*8+7
    int rowBase = blockIdx.x * BM;
    int q       = blockIdx.y;
    int t0      = q * TPQ;

    // --- prologue: A dup tile (128KB = 8192 chunks -> 64 iters) + B t0, t0+1 ---
    {
        const char* srcA = (const char*)(g_xD + (size_t)blockIdx.x * (DD * 256));
#pragma unroll
        for (int j = 0; j < 64; j++) {
            int i = tid + NTHREADS * j;
            cpa16(sbA + i * 16, srcA + i * 16);
        }
        copy_tile_32k(sbB, (const char*)(g_pT + (size_t)t0 * (DD * BN)), tid);
        if (tid < BN) p2s[tid] = g_p2[t0 * BN + tid];
        x2s[tid] = g_x2[rowBase + tid];
        CP_COMMIT();
        copy_tile_32k(sbB + DD * BN * 4,
                      (const char*)(g_pT + (size_t)(t0 + 1) * (DD * BN)), tid);
        if (tid < BN) p2s[BN + tid] = g_p2[(t0 + 1) * BN + tid];
        CP_COMMIT();
    }

    CP_WAIT(1);
    __syncthreads();
    float x2r[TM];
#pragma unroll
    for (int i = 0; i < TM; i++) x2r[i] = x2s[ty * TM + i];

    float bestv[TM]; int besti[TM];
#pragma unroll
    for (int i = 0; i < TM; i++) { bestv[i] = 3.0e38f; besti[i] = 0; }

    const float* xb = As + ty * 16;             // 8 rows dup = 16 floats

    for (int tl = 0; tl < TPQ; tl++) {
        int t = t0 + tl;
        int b = tl & 1;
        if (tl > 0) {
            if (tl == TPQ - 1) { CP_WAIT(0); } else { CP_WAIT(1); }
            __syncthreads();
        }

        uint64_t acc[TM][4];                    // [row][k-pair]
#pragma unroll
        for (int i = 0; i < TM; i++)
#pragma unroll
            for (int j = 0; j < 4; j++) acc[i][j] = 0ull;

        const float* pb = Bs + b * (DD * BN) + tx * 4;
#pragma unroll 4
        for (int d = 0; d < DD; d++) {
            ulonglong2 A0 = *(const ulonglong2*)(xb + d * 256);        // rows 0,1
            ulonglong2 A1 = *(const ulonglong2*)(xb + d * 256 + 4);    // rows 2,3
            ulonglong2 A2 = *(const ulonglong2*)(xb + d * 256 + 8);    // rows 4,5
            ulonglong2 A3 = *(const ulonglong2*)(xb + d * 256 + 12);   // rows 6,7
            ulonglong2 B0 = *(const ulonglong2*)(pb + d * BN);         // k+0/1, k+2/3
            ulonglong2 B1 = *(const ulonglong2*)(pb + d * BN + 32);    // k+32.., k+34..
            uint64_t ar[TM] = { A0.x, A0.y, A1.x, A1.y, A2.x, A2.y, A3.x, A3.y };
            uint64_t bv[4]  = { B0.x, B0.y, B1.x, B1.y };
#pragma unroll
            for (int i = 0; i < TM; i++)
#pragma unroll
                for (int j = 0; j < 4; j++)
                    acc[i][j] = ffma2(ar[i], bv[j], acc[i][j]);
        }

        // epilogue: j ascending -> k ascending within thread; strict '<' = first-min
#pragma unroll
        for (int j = 0; j < 4; j++) {
            int koff = tx * 4 + (j >> 1) * 32 + (j & 1) * 2;
            int kg = t * BN + koff;
            float p0 = p2s[b * BN + koff];
            float p1 = p2s[b * BN + koff + 1];
#pragma unroll
            for (int i = 0; i < TM; i++) {
                float2 dp = unpack2(acc[i][j]);
                float s0 = (x2r[i] - 2.0f * dp.x) + p0;
                float s1 = (x2r[i] - 2.0f * dp.y) + p1;
                if (s0 < bestv[i]) { bestv[i] = s0; besti[i] = kg; }
                if (s1 < bestv[i]) { bestv[i] = s1; besti[i] = kg + 1; }
            }
        }
        __syncthreads();

        if (tl + 2 < TPQ) {
            copy_tile_32k(sbB + b * (DD * BN * 4),
                          (const char*)(g_pT + (size_t)(t + 2) * (DD * BN)), tid);
            if (tid < BN) p2s[b * BN + tid] = g_p2[(t + 2) * BN + tid];
            CP_COMMIT();
        }
    }

    // --- cross-thread reduction: 8 candidates per row (reuse B region) ---
    float* redv = Bs;                     // [8][BM]
    int*   redi = (int*)(Bs + 8 * BM);    // [8][BM]
#pragma unroll
    for (int i = 0; i < TM; i++) {
        int row = ty * TM + i;
        redv[tx * BM + row] = bestv[i];
        redi[tx * BM + row] = besti[i];
    }
    __syncthreads();
    {
        float bv = 3.4e38f; int bi = 0x7fffffff;
#pragma unroll
        for (int t = 0; t < 8; t++) {
            float v  = redv[t * BM + tid];
            int   ix = redi[t * BM + tid];
            if (v < bv || (v == bv && ix < bi)) { bv = v; bi = ix; }
        }
        g_partv[q * NN + rowBase + tid] = bv;
        g_parti[q * NN + rowBase + tid] = bi;
    }
}

// ---------------- merge quarters (disjoint ascending k-ranges) ----------
__global__ void merge_kernel() {
    int row = blockIdx.x * 256 + threadIdx.x;
    float bv = g_partv[row];
    int   bi = g_parti[row];
#pragma unroll
    for (int qq = 1; qq < NSPLIT; qq++) {
        float v  = g_partv[qq * NN + row];
        int   ix = g_parti[qq * NN + row];
        if (v < bv) { bv = v; bi = ix; }
    }
    g_idx[row] = bi;
}

// ---------------- gather ----------------
__global__ void gather_kernel(const float* __restrict__ x, const float* __restrict__ p,
                              const float* __restrict__ lab, float* __restrict__ out) {
    int row = blockIdx.x;
    int tid = threadIdx.x;
    int idx = g_idx[row];

    const float4* xr = (const float4*)(x + (size_t)row * DD);
    float4*       o0 = (float4*)(out + (size_t)row * DD);
    const float4* pr = (const float4*)(p + (size_t)idx * DD);
    float4*       o1 = (float4*)(out + (size_t)NN * DD + (size_t)row * DD);
    const float4* lr = (const float4*)(lab + (size_t)idx * CC);
    float4*       o2 = (float4*)(out + 2 * (size_t)NN * DD + (size_t)row * CC);

    if (tid < 32)       __stcs(o0 + tid,      xr[tid]);
    else if (tid < 64)  __stcs(o1 + tid - 32, pr[tid - 32]);
    for (int i = tid; i < CC / 4; i += blockDim.x) __stcs(o2 + i, lr[i]);
}

// ---------------- launch ----------------
extern "C" void kernel_launch(void* const* d_in, const int* in_sizes, int n_in,
                              void* d_out, int out_size) {
    const float* x   = (const float*)d_in[0];
    const float* p   = (const float*)d_in[1];
    const float* lab = (const float*)d_in[2];
    float* out = (float*)d_out;

    float *px2 = nullptr, *pp2 = nullptr;
    cudaGetSymbolAddress((void**)&px2, g_x2);
    cudaGetSymbolAddress((void**)&pp2, g_p2);

    cudaFuncSetAttribute(argmin_kernel, cudaFuncAttributeMaxDynamicSharedMemorySize, SMEM_BYTES);

    row_norm_kernel<<<NN / 8, 256>>>(x, px2, NN);
    prep_x_kernel<<<NN * 32 / 256, 256>>>(x);
    prep_p_kernel<<<KPAD * 16 / 256, 256>>>(p);
    row_norm_kernel<<<(KK + 7) / 8, 256>>>(p, pp2, KK);
    argmin_kernel<<<dim3(NN / BM, NSPLIT), NTHREADS, SMEM_BYTES>>>();
    merge_kernel<<<NN / 256, 256>>>();
    gather_kernel<<<NN, 256>>>(x, p, lab, out);
}